// round 7
// baseline (speedup 1.0000x reference)
#include <cuda_runtime.h>
#include <cstdint>

// ---------------------------------------------------------------------------
// MoE router: 3xTF32 mma.sync GEMM (16384x64x2048) + fused softmax/top-2.
// sm_80-compatible PTX only. R7: TM=32 (grid 512, 3-4 CTAs/SM), 3-stage
// cp.async pipeline (1 barrier/tile), merged slab accumulator:
//   per 32-K slab: accS += Ah*Bh (exact products) + Ah*Bl + Al*Bh,
//   then accT += accS (rn). Chain error ~5e-7 relative.
// ---------------------------------------------------------------------------

namespace {
constexpr int TOKENS = 16384;
constexpr int DK     = 2048;
constexpr int E      = 64;
constexpr int TM     = 32;         // tokens per CTA
constexpr int KC     = 32;         // K per pipeline stage (= slab)
constexpr int NTILES = DK / KC;    // 64
constexpr int NT     = 128;        // threads per CTA (4 warps)
constexpr int STAGES = 3;

constexpr size_t OFF_PROBS = (size_t)TOKENS * E;
constexpr size_t OFF_TKP   = OFF_PROBS + (size_t)TOKENS * E;
constexpr size_t OFF_TKI   = OFF_TKP + (size_t)TOKENS * 2;

constexpr int A_STAGE = 4096;      // 32x32 f32
constexpr int B_BASE  = STAGES * A_STAGE;   // 12288
constexpr int B_STAGE = 8192;      // 32x64 f32
constexpr int SMEM_SZ = B_BASE + STAGES * B_STAGE;  // 36864
}

__device__ __forceinline__ uint32_t smem_u32(const void* p) {
    uint32_t a;
    asm("{ .reg .u64 t; cvta.to.shared.u64 t, %1; cvt.u32.u64 %0, t; }" : "=r"(a) : "l"(p));
    return a;
}
__device__ __forceinline__ void cp16(uint32_t s, const void* g) {
    asm volatile("cp.async.cg.shared.global [%0], [%1], 16;" :: "r"(s), "l"(g));
}
#define CP_COMMIT() asm volatile("cp.async.commit_group;" ::: "memory")
#define CP_WAIT1()  asm volatile("cp.async.wait_group 1;" ::: "memory")
#define CP_WAIT0()  asm volatile("cp.async.wait_group 0;" ::: "memory")

#define MMA8(c, a, b)                                                          \
    asm volatile(                                                              \
        "mma.sync.aligned.m16n8k8.row.col.f32.tf32.tf32.f32 "                  \
        "{%0,%1,%2,%3}, {%4,%5,%6,%7}, {%8,%9}, {%0,%1,%2,%3};"                \
        : "+f"((c)[0]), "+f"((c)[1]), "+f"((c)[2]), "+f"((c)[3])               \
        : "r"((a)[0]), "r"((a)[1]), "r"((a)[2]), "r"((a)[3]),                  \
          "r"((b)[0]), "r"((b)[1]))

__global__ __launch_bounds__(NT, 4) void moe_router_mma(
    const float* __restrict__ x, const float* __restrict__ W, float* __restrict__ out)
{
    __shared__ __align__(16) char smem[SMEM_SZ];
    const uint32_t sbase = smem_u32(smem);

    const int tid  = threadIdx.x;
    const int wid  = tid >> 5;        // 0..3
    const int lane = tid & 31;
    const int wm   = wid >> 1;        // warp row: tokens [wm*16, +16)
    const int wn   = wid & 1;         // warp col: experts [wn*32, +32)
    const int g    = lane >> 2;
    const int tig  = lane & 3;
    const int tokBase = blockIdx.x * TM;

    float accT[4][4];                 // running logit total (chain of slabs)
    #pragma unroll
    for (int nt = 0; nt < 4; nt++)
        #pragma unroll
        for (int i = 0; i < 4; i++) accT[nt][i] = 0.f;

    // A[row 0..31][chunk 0..7 of 4 floats], phys chunk = chunk ^ (row&7)
    // B[k 0..31][chunk 0..15 of 4 floats],  phys chunk = chunk ^ (2*(k&3))
    auto issue = [&](int t) {
        const int st = t % STAGES;
        const uint32_t Ab = sbase + st * A_STAGE;
        const uint32_t Bb = sbase + B_BASE + st * B_STAGE;
        const float* xt = x + (size_t)tokBase * DK + t * KC;
        #pragma unroll
        for (int j = 0; j < 2; j++) {
            int idx = tid + j * NT;                 // 0..255
            int row = idx >> 3, ch = idx & 7;
            cp16(Ab + row * 128 + ((ch ^ (row & 7)) << 4),
                 xt + (size_t)row * DK + ch * 4);
        }
        const float* wt = W + (size_t)t * KC * E;
        #pragma unroll
        for (int j = 0; j < 4; j++) {
            int idx = tid + j * NT;                 // 0..511
            int k = idx >> 4, ch = idx & 15;
            cp16(Bb + k * 256 + ((ch ^ (2 * (k & 3))) << 4),
                 wt + (size_t)k * E + ch * 4);
        }
    };

    issue(0); CP_COMMIT();
    issue(1); CP_COMMIT();

    for (int t = 0; t < NTILES; t++) {
        if (t + 2 < NTILES) { CP_WAIT1(); } else { CP_WAIT0(); }
        __syncthreads();
        if (t + 2 < NTILES) { issue(t + 2); CP_COMMIT(); }

        const int st = t % STAGES;
        const uint32_t Ab = sbase + st * A_STAGE;
        const uint32_t Bb = sbase + B_BASE + st * B_STAGE;

        // per-slab accumulator: exact hi*hi products + tiny cross terms
        float accS[4][4];
        #pragma unroll
        for (int nt = 0; nt < 4; nt++)
            #pragma unroll
            for (int i = 0; i < 4; i++) accS[nt][i] = 0.f;

        #pragma unroll
        for (int ks = 0; ks < 4; ks++) {
            uint32_t ahi[4], alo[4];
            #pragma unroll
            for (int i = 0; i < 4; i++) {
                int row = wm * 16 + g + (i & 1) * 8;
                int ch  = (i >> 1) + 2 * ks;
                uint32_t addr = Ab + row * 128 + ((ch ^ (row & 7)) << 4) + tig * 4;
                uint32_t raw;
                asm volatile("ld.shared.b32 %0, [%1];" : "=r"(raw) : "r"(addr));
                uint32_t hb = raw & 0xffffe000u;
                float lo = __uint_as_float(raw) - __uint_as_float(hb);
                ahi[i] = hb;
                alo[i] = __float_as_uint(lo);
            }
            uint32_t bhi[4][2], blo[4][2];
            #pragma unroll
            for (int nt = 0; nt < 4; nt++) {
                #pragma unroll
                for (int ib = 0; ib < 2; ib++) {
                    int k = ks * 8 + ib * 4 + tig;
                    int n = wn * 32 + nt * 8 + g;
                    int ch = n >> 2;
                    uint32_t addr = Bb + k * 256 + ((ch ^ (2 * tig)) << 4) + (n & 3) * 4;
                    uint32_t raw;
                    asm volatile("ld.shared.b32 %0, [%1];" : "=r"(raw) : "r"(addr));
                    uint32_t hb = raw & 0xffffe000u;
                    float lo = __uint_as_float(raw) - __uint_as_float(hb);
                    bhi[nt][ib] = hb;
                    blo[nt][ib] = __float_as_uint(lo);
                }
            }
            #pragma unroll
            for (int nt = 0; nt < 4; nt++) {
                MMA8(accS[nt], ahi, bhi[nt]);   // exact products
                MMA8(accS[nt], ahi, blo[nt]);   // tiny cross terms
                MMA8(accS[nt], alo, bhi[nt]);
            }
        }

        // fold slab into running total (one rn-add per accumulator element)
        #pragma unroll
        for (int nt = 0; nt < 4; nt++)
            #pragma unroll
            for (int i = 0; i < 4; i++)
                accT[nt][i] = __fadd_rn(accT[nt][i], accS[nt][i]);
    }
    __syncthreads();

    // ---- epilogue: logits -> smem [32][66] ----
    float* L = (float*)smem;
    #pragma unroll
    for (int nt = 0; nt < 4; nt++) {
        int row0 = wm * 16 + g;
        int col  = wn * 32 + nt * 8 + tig * 2;
        *(float2*)&L[row0 * 66 + col]       = make_float2(accT[nt][0], accT[nt][1]);
        *(float2*)&L[(row0 + 8) * 66 + col] = make_float2(accT[nt][2], accT[nt][3]);
    }
    __syncthreads();

    if (tid < TM) {
        const int token = tokBase + tid;
        float* lrow = &L[tid * 66];

        float l[64];
        #pragma unroll
        for (int e = 0; e < 64; e++) l[e] = lrow[e];

        // top-2; strict '>' keeps lower index on ties (matches lax.top_k)
        float m1 = -1e30f, m2 = -1e30f;
        int   i1 = 0,      i2 = 0;
        #pragma unroll
        for (int e = 0; e < 64; e++) {
            float v = l[e];
            if (v > m1)      { m2 = m1; i2 = i1; m1 = v; i1 = e; }
            else if (v > m2) { m2 = v;  i2 = e; }
        }

        float sum = 0.f;
        #pragma unroll
        for (int e = 0; e < 64; e++) { l[e] = expf(l[e] - m1); sum += l[e]; }
        const float inv = 1.0f / sum;

        float4* prow = (float4*)&out[OFF_PROBS + (size_t)token * 64];
        float4* drow = (float4*)&out[(size_t)token * 64];
        #pragma unroll
        for (int gq = 0; gq < 16; gq++) {
            float4 pv;
            pv.x = l[gq*4+0] * inv; pv.y = l[gq*4+1] * inv;
            pv.z = l[gq*4+2] * inv; pv.w = l[gq*4+3] * inv;
            prow[gq] = pv;
            float d0 = 0.f, d1 = 0.f, d2 = 0.f, d3 = 0.f;
            if ((i1 >> 2) == gq) { int r = i1 & 3; if (r==0) d0=1.f; else if (r==1) d1=1.f; else if (r==2) d2=1.f; else d3=1.f; }
            if ((i2 >> 2) == gq) { int r = i2 & 3; if (r==0) d0+=1.f; else if (r==1) d1+=1.f; else if (r==2) d2+=1.f; else d3+=1.f; }
            drow[gq] = make_float4(d0, d1, d2, d3);
        }
        out[OFF_TKP + (size_t)token * 2 + 0] = l[i1] * inv;
        out[OFF_TKP + (size_t)token * 2 + 1] = l[i2] * inv;
        out[OFF_TKI + (size_t)token * 2 + 0] = (float)i1;
        out[OFF_TKI + (size_t)token * 2 + 1] = (float)i2;
    }
}

extern "C" void kernel_launch(void* const* d_in, const int* in_sizes, int n_in,
                              void* d_out, int out_size) {
    const float* x = (const float*)d_in[0];
    const float* W = (const float*)d_in[1];
    float* out = (float*)d_out;
    moe_router_mma<<<TOKENS / TM, NT>>>(x, W, out);
}

// round 10
// speedup vs baseline: 1.1141x; 1.1141x over previous
#include <cuda_runtime.h>
#include <cstdint>

// ---------------------------------------------------------------------------
// MoE router: 3xTF32 mma.sync GEMM (16384x64x2048) + fused softmax/top-2.
// sm_80-compatible PTX only. R8 = R6 shape (TM=64, 128thr, grid 256, occ 2)
// + 3-stage cp.async pipeline with ONE barrier per tile
// + pass-grouped MMA ordering (dependency spacing 8 instead of 1).
// Precision (proven in R5/R6): accS = exact hi*hi slab sums, folded rn;
// accL = small-magnitude cross terms, added once at the end.
// ---------------------------------------------------------------------------

namespace {
constexpr int TOKENS = 16384;
constexpr int DK     = 2048;
constexpr int E      = 64;
constexpr int TM     = 64;         // tokens per CTA
constexpr int KC     = 32;         // K per pipeline stage (= slab)
constexpr int NTILES = DK / KC;    // 64
constexpr int NT     = 128;        // threads per CTA (4 warps)
constexpr int STAGES = 3;

constexpr size_t OFF_PROBS = (size_t)TOKENS * E;
constexpr size_t OFF_TKP   = OFF_PROBS + (size_t)TOKENS * E;
constexpr size_t OFF_TKI   = OFF_TKP + (size_t)TOKENS * 2;

constexpr int A_STAGE = 8192;                      // 64x32 f32
constexpr int B_BASE  = STAGES * A_STAGE;          // 24576
constexpr int B_STAGE = 8192;                      // 32x64 f32
constexpr int SMEM_SZ = B_BASE + STAGES * B_STAGE; // 49152 (= 48KB static max)
}

__device__ __forceinline__ uint32_t smem_u32(const void* p) {
    uint32_t a;
    asm("{ .reg .u64 t; cvta.to.shared.u64 t, %1; cvt.u32.u64 %0, t; }" : "=r"(a) : "l"(p));
    return a;
}
__device__ __forceinline__ void cp16(uint32_t s, const void* g) {
    asm volatile("cp.async.cg.shared.global [%0], [%1], 16;" :: "r"(s), "l"(g));
}
#define CP_COMMIT() asm volatile("cp.async.commit_group;" ::: "memory")
#define CP_WAIT1()  asm volatile("cp.async.wait_group 1;" ::: "memory")
#define CP_WAIT0()  asm volatile("cp.async.wait_group 0;" ::: "memory")

#define MMA8(c, a, b)                                                          \
    asm volatile(                                                              \
        "mma.sync.aligned.m16n8k8.row.col.f32.tf32.tf32.f32 "                  \
        "{%0,%1,%2,%3}, {%4,%5,%6,%7}, {%8,%9}, {%0,%1,%2,%3};"                \
        : "+f"((c)[0]), "+f"((c)[1]), "+f"((c)[2]), "+f"((c)[3])               \
        : "r"((a)[0]), "r"((a)[1]), "r"((a)[2]), "r"((a)[3]),                  \
          "r"((b)[0]), "r"((b)[1]))

__global__ __launch_bounds__(NT, 2) void moe_router_mma(
    const float* __restrict__ x, const float* __restrict__ W, float* __restrict__ out)
{
    __shared__ __align__(16) char smem[SMEM_SZ];
    const uint32_t sbase = smem_u32(smem);

    const int tid  = threadIdx.x;
    const int wid  = tid >> 5;        // 0..3
    const int lane = tid & 31;
    const int wm   = wid >> 1;        // warp row: tokens [wm*32, +32)
    const int wn   = wid & 1;         // warp col: experts [wn*32, +32)
    const int g    = lane >> 2;
    const int tig  = lane & 3;
    const int tokBase = blockIdx.x * TM;

    float accT[2][4][4];   // hi-pass running total (chain of exact slabs)
    float accL[2][4][4];   // cross-pass accumulator, small magnitude
    #pragma unroll
    for (int mt = 0; mt < 2; mt++)
        #pragma unroll
        for (int nt = 0; nt < 4; nt++)
            #pragma unroll
            for (int i = 0; i < 4; i++) { accT[mt][nt][i] = 0.f; accL[mt][nt][i] = 0.f; }

    // A[row 0..63][chunk 0..7 of 4 floats], phys chunk = chunk ^ (row&7)
    // B[k 0..31][chunk 0..15 of 4 floats],  phys chunk = chunk ^ (2*(k&3))
    auto issue = [&](int t) {
        const int st = t % STAGES;
        const uint32_t Ab = sbase + st * A_STAGE;
        const uint32_t Bb = sbase + B_BASE + st * B_STAGE;
        const float* xt = x + (size_t)tokBase * DK + t * KC;
        #pragma unroll
        for (int j = 0; j < 4; j++) {
            int idx = tid + j * NT;                 // 0..511
            int row = idx >> 3, ch = idx & 7;
            cp16(Ab + row * 128 + ((ch ^ (row & 7)) << 4),
                 xt + (size_t)row * DK + ch * 4);
        }
        const float* wt = W + (size_t)t * KC * E;
        #pragma unroll
        for (int j = 0; j < 4; j++) {
            int idx = tid + j * NT;                 // 0..511
            int k = idx >> 4, ch = idx & 15;
            cp16(Bb + k * 256 + ((ch ^ (2 * (k & 3))) << 4),
                 wt + (size_t)k * E + ch * 4);
        }
    };

    issue(0); CP_COMMIT();
    issue(1); CP_COMMIT();

    for (int t = 0; t < NTILES; t++) {
        if (t + 2 < NTILES) { CP_WAIT1(); } else { CP_WAIT0(); }
        __syncthreads();   // stage t data visible to all; stage t-1 free to overwrite
        if (t + 2 < NTILES) { issue(t + 2); CP_COMMIT(); }

        const int st = t % STAGES;
        const uint32_t Ab = sbase + st * A_STAGE;
        const uint32_t Bb = sbase + B_BASE + st * B_STAGE;

        // per-slab hi accumulator (exact tf32 products, 32 K-terms)
        float accS[2][4][4];
        #pragma unroll
        for (int mt = 0; mt < 2; mt++)
            #pragma unroll
            for (int nt = 0; nt < 4; nt++)
                #pragma unroll
                for (int i = 0; i < 4; i++) accS[mt][nt][i] = 0.f;

        #pragma unroll
        for (int ks = 0; ks < 4; ks++) {
            uint32_t ahi[2][4], alo[2][4];
            #pragma unroll
            for (int mt = 0; mt < 2; mt++) {
                #pragma unroll
                for (int i = 0; i < 4; i++) {
                    int row = wm * 32 + mt * 16 + g + (i & 1) * 8;
                    int ch  = (i >> 1) + 2 * ks;
                    uint32_t addr = Ab + row * 128 + ((ch ^ (row & 7)) << 4) + tig * 4;
                    uint32_t raw;
                    asm volatile("ld.shared.b32 %0, [%1];" : "=r"(raw) : "r"(addr));
                    uint32_t hb = raw & 0xffffe000u;
                    float lo = __uint_as_float(raw) - __uint_as_float(hb);
                    ahi[mt][i] = hb;
                    alo[mt][i] = __float_as_uint(lo);
                }
            }
            uint32_t bhi[4][2], blo[4][2];
            #pragma unroll
            for (int nt = 0; nt < 4; nt++) {
                #pragma unroll
                for (int ib = 0; ib < 2; ib++) {
                    int k = ks * 8 + ib * 4 + tig;
                    int n = wn * 32 + nt * 8 + g;
                    int ch = n >> 2;
                    uint32_t addr = Bb + k * 256 + ((ch ^ (2 * tig)) << 4) + (n & 3) * 4;
                    uint32_t raw;
                    asm volatile("ld.shared.b32 %0, [%1];" : "=r"(raw) : "r"(addr));
                    uint32_t hb = raw & 0xffffe000u;
                    float lo = __uint_as_float(raw) - __uint_as_float(hb);
                    bhi[nt][ib] = hb;
                    blo[nt][ib] = __float_as_uint(lo);
                }
            }
            // pass-grouped: same-register MMAs are 8 apart (latency covered)
            #pragma unroll
            for (int mt = 0; mt < 2; mt++)
                #pragma unroll
                for (int nt = 0; nt < 4; nt++)
                    MMA8(accS[mt][nt], ahi[mt], bhi[nt]);   // exact products
            #pragma unroll
            for (int mt = 0; mt < 2; mt++)
                #pragma unroll
                for (int nt = 0; nt < 4; nt++)
                    MMA8(accL[mt][nt], ahi[mt], blo[nt]);   // cross term 1
            #pragma unroll
            for (int mt = 0; mt < 2; mt++)
                #pragma unroll
                for (int nt = 0; nt < 4; nt++)
                    MMA8(accL[mt][nt], alo[mt], bhi[nt]);   // cross term 2
        }

        // fold slab into running total (one rn-add per accumulator)
        #pragma unroll
        for (int mt = 0; mt < 2; mt++)
            #pragma unroll
            for (int nt = 0; nt < 4; nt++)
                #pragma unroll
                for (int i = 0; i < 4; i++)
                    accT[mt][nt][i] = __fadd_rn(accT[mt][nt][i], accS[mt][nt][i]);
    }
    __syncthreads();

    // ---- epilogue: logits = T + L -> smem [64][66] ----
    float* L = (float*)smem;
    #pragma unroll
    for (int mt = 0; mt < 2; mt++) {
        #pragma unroll
        for (int nt = 0; nt < 4; nt++) {
            int row0 = wm * 32 + mt * 16 + g;
            int col  = wn * 32 + nt * 8 + tig * 2;
            float v0 = __fadd_rn(accT[mt][nt][0], accL[mt][nt][0]);
            float v1 = __fadd_rn(accT[mt][nt][1], accL[mt][nt][1]);
            float v2 = __fadd_rn(accT[mt][nt][2], accL[mt][nt][2]);
            float v3 = __fadd_rn(accT[mt][nt][3], accL[mt][nt][3]);
            *(float2*)&L[row0 * 66 + col]       = make_float2(v0, v1);
            *(float2*)&L[(row0 + 8) * 66 + col] = make_float2(v2, v3);
        }
    }
    __syncthreads();

    if (tid < TM) {
        const int token = tokBase + tid;
        float* lrow = &L[tid * 66];

        float l[64];
        #pragma unroll
        for (int e = 0; e < 64; e++) l[e] = lrow[e];

        // top-2; strict '>' keeps lower index on ties (matches lax.top_k)
        float m1 = -1e30f, m2 = -1e30f;
        int   i1 = 0,      i2 = 0;
        #pragma unroll
        for (int e = 0; e < 64; e++) {
            float v = l[e];
            if (v > m1)      { m2 = m1; i2 = i1; m1 = v; i1 = e; }
            else if (v > m2) { m2 = v;  i2 = e; }
        }

        float sum = 0.f;
        #pragma unroll
        for (int e = 0; e < 64; e++) { l[e] = expf(l[e] - m1); sum += l[e]; }
        const float inv = 1.0f / sum;

        float4* prow = (float4*)&out[OFF_PROBS + (size_t)token * 64];
        float4* drow = (float4*)&out[(size_t)token * 64];
        #pragma unroll
        for (int gq = 0; gq < 16; gq++) {
            float4 pv;
            pv.x = l[gq*4+0] * inv; pv.y = l[gq*4+1] * inv;
            pv.z = l[gq*4+2] * inv; pv.w = l[gq*4+3] * inv;
            prow[gq] = pv;
            float d0 = 0.f, d1 = 0.f, d2 = 0.f, d3 = 0.f;
            if ((i1 >> 2) == gq) { int r = i1 & 3; if (r==0) d0=1.f; else if (r==1) d1=1.f; else if (r==2) d2=1.f; else d3=1.f; }
            if ((i2 >> 2) == gq) { int r = i2 & 3; if (r==0) d0+=1.f; else if (r==1) d1+=1.f; else if (r==2) d2+=1.f; else d3+=1.f; }
            drow[gq] = make_float4(d0, d1, d2, d3);
        }
        out[OFF_TKP + (size_t)token * 2 + 0] = l[i1] * inv;
        out[OFF_TKP + (size_t)token * 2 + 1] = l[i2] * inv;
        out[OFF_TKI + (size_t)token * 2 + 0] = (float)i1;
        out[OFF_TKI + (size_t)token * 2 + 1] = (float)i2;
    }
}

extern "C" void kernel_launch(void* const* d_in, const int* in_sizes, int n_in,
                              void* d_out, int out_size) {
    const float* x = (const float*)d_in[0];
    const float* W = (const float*)d_in[1];
    float* out = (float*)d_out;
    moe_router_mma<<<TOKENS / TM, NT>>>(x, W, out);
}